// round 7
// baseline (speedup 1.0000x reference)
#include <cuda_runtime.h>

#define HH 512
#define WW 512
#define KS 32
#define PD 16            // KS/2
#define RC 8             // rows per chunk (16 scan arrays = 16 warps)
#define RPB 128          // output rows per block
#define NT 512           // one thread per real column
#define SPITCH 544       // f(c) = c + (c>>4): 0..511 -> 0..542; slot 543 = zero
#define ZSLOT 543
#define BUFSZ (2 * RC * SPITCH)          // one ping-pong buffer pair (S+Q)
#define SMEM_FLOATS (2 * BUFSZ)          // 69632 B

__device__ __forceinline__ float frsqrt(float v) {
    float r;
    asm("rsqrt.approx.f32 %0, %1;" : "=f"(r) : "f"(v));
    return r;
}

__global__ __launch_bounds__(NT, 3)
void localnorm_v7(const float* __restrict__ x, float* __restrict__ out) {
    extern __shared__ float smem[];      // [2][2][RC][SPITCH]: S0,Q0,S1,Q1

    const int tid  = threadIdx.x;
    const int lane = tid & 31;
    const int wid  = tid >> 5;
    const int r0   = blockIdx.x * RPB;

    const float* __restrict__ X = x   + (size_t)blockIdx.y * (HH * WW);
    float* __restrict__       O = out + (size_t)blockIdx.y * (HH * WW);

    // zero all four arrays' "P[-1]" slots (rows 0..31 across S0,Q0,S1,Q1)
    if (tid < 4 * RC) smem[tid * SPITCH + ZSLOT] = 0.f;

    // ---- init vertical window: rows r0-16 .. r0+15 (lower reflect only) ----
    float vs = 0.f, vq = 0.f;
    #pragma unroll
    for (int d = -PD; d < PD; d++) {
        int rr = abs(r0 + d);
        float v = X[(rr << 9) + tid];
        vs += v; vq = fmaf(v, v, vq);
    }

    const int fcol = tid + (tid >> 4);
    const float inv_n = 1.f / (float)(KS * KS);

    // ---- phase-C per-thread constants (oc == tid) ----
    const int oc  = tid;
    int hi = oc + 15; if (hi > 511) hi = 511;
    const int fhi = hi + (hi >> 4);
    const int lo  = oc - 17;
    const int flo = (lo >= 0) ? (lo + (lo >> 4)) : ZSLOT;     // P[-1] == 0
    const bool leftE  = (oc <= 15);
    const bool rightE = (oc >= 497);
    const int fle  = leftE  ? ((16 - oc) + ((16 - oc) >> 4)) : 0;
    const int fre2 = rightE ? ((1006 - oc) + ((1006 - oc) >> 4)) : 0;

    // ---- phase A: emit RC rows of vertical sums into (bS,bQ); slide window ----
    auto phaseA = [&](int ibase, float* bS, float* bQ) {
        if (ibase >= PD && ibase + RC + PD <= HH) {
            // interior: pure streaming, immediate-offset loads
            const float* pa = X + ((ibase + PD) << 9) + tid;
            const float* pb = X + ((ibase - PD) << 9) + tid;
            #pragma unroll
            for (int rr = 0; rr < RC; rr++) {
                bS[rr * SPITCH + fcol] = vs;
                bQ[rr * SPITCH + fcol] = vq;
                float va = pa[rr << 9];
                float vb = pb[rr << 9];
                vs += va - vb;
                vq = fmaf(va, va, fmaf(-vb, vb, vq));
            }
        } else {
            #pragma unroll
            for (int rr = 0; rr < RC; rr++) {
                bS[rr * SPITCH + fcol] = vs;
                bQ[rr * SPITCH + fcol] = vq;
                int i  = ibase + rr;
                int ru = i + PD; ru = (ru < HH) ? ru : (2 * HH - 2 - ru);
                int rd = abs(i - PD);
                float va = X[(ru << 9) + tid];
                float vb = X[(rd << 9) + tid];
                vs += va - vb;
                vq = fmaf(va, va, fmaf(-vb, vb, vq));
            }
        }
    };

    phaseA(r0, smem, smem + RC * SPITCH);            // prologue into buffer 0

    #pragma unroll 1
    for (int k = 0; k < RPB / RC; k++) {
        float* bS = smem + (k & 1) * BUFSZ;
        float* bQ = bS + RC * SPITCH;
        const int ibase = r0 + k * RC;

        __syncthreads();                              // A(k) complete

        // ---- phase B: 16 warps, one (row,array) each; values held in regs ----
        {
            float* V = ((wid & 1) ? bQ : bS) + (wid >> 1) * SPITCH + lane * 17;
            float rv[16];
            float run = 0.f;
            #pragma unroll
            for (int j = 0; j < 16; j++) { rv[j] = V[j]; run += rv[j]; }
            float tot = run;
            #pragma unroll
            for (int s = 1; s < 32; s <<= 1) {
                float u = __shfl_up_sync(0xffffffffu, tot, s);
                if (lane >= s) tot += u;
            }
            float acc = tot - run;                    // exclusive offset
            #pragma unroll
            for (int j = 0; j < 16; j++) {
                acc += rv[j];
                V[j] = acc;
            }
        }
        __syncthreads();                              // B(k) complete

        // ---- A(k+1) into other buffer (LDGs overlap C's LDS waits) ----
        if (k + 1 < RPB / RC) {
            float* nS = smem + ((k + 1) & 1) * BUFSZ;
            phaseA(ibase + RC, nS, nS + RC * SPITCH);
        }

        // ---- phase C: box[oc] = P[hi]-P[lo] (+ edge terms); finalize ----
        const float* Xc = X + (ibase << 9) + tid;
        float*       Oc = O + (ibase << 9) + tid;
        #pragma unroll
        for (int rr = 0; rr < RC; rr++) {
            const float* pS = bS + rr * SPITCH;
            const float* pQ = bQ + rr * SPITCH;
            float bSv = pS[fhi] - pS[flo];
            float bQv = pQ[fhi] - pQ[flo];
            if (leftE)  { bSv += pS[fle] - pS[0];    bQv += pQ[fle] - pQ[0]; }
            if (rightE) { bSv += pS[541] - pS[fre2]; bQv += pQ[541] - pQ[fre2]; }
            float mean = bSv * inv_n;
            float msq  = bQv * inv_n;
            float xc   = Xc[rr << 9];
            float var  = fabsf(fmaf(-mean, mean, msq));
            float r    = (xc - mean) * frsqrt(var + 1e-20f);
            r = fminf(fmaxf(r, -6.f), 6.f);
            Oc[rr << 9] = r;
        }
    }
}

extern "C" void kernel_launch(void* const* d_in, const int* in_sizes, int n_in,
                              void* d_out, int out_size) {
    const float* x = (const float*)d_in[0];
    float* out = (float*)d_out;
    const int n_img = in_sizes[0] / (HH * WW);        // 96
    const int smem_bytes = SMEM_FLOATS * (int)sizeof(float);   // 69632

    cudaFuncSetAttribute(localnorm_v7,
                         cudaFuncAttributeMaxDynamicSharedMemorySize, smem_bytes);

    dim3 grid(HH / RPB, n_img);                       // 4 x 96 = 384 blocks
    localnorm_v7<<<grid, NT, smem_bytes>>>(x, out);
}

// round 8
// speedup vs baseline: 1.0930x; 1.0930x over previous
#include <cuda_runtime.h>

#define HH 512
#define WW 512
#define KS 32
#define PD 16            // KS/2
#define RC 8             // rows per chunk (16 scan arrays = 16 warps)
#define NT 512           // one thread per real column
#define SPITCH 544       // f(c) = c + (c>>4): 0..511 -> 0..542; slot 543 = zero
#define ZSLOT 543

__device__ __forceinline__ float frsqrt(float v) {
    float r;
    asm("rsqrt.approx.f32 %0, %1;" : "=f"(r) : "f"(v));
    return r;
}

__global__ __launch_bounds__(NT, 3)
void localnorm_v8(const float* __restrict__ x, float* __restrict__ out) {
    __shared__ float sS[RC * SPITCH];   // vertical sums of x   -> in-place prefix
    __shared__ float sQ[RC * SPITCH];   // vertical sums of x^2 -> in-place prefix

    const int tid  = threadIdx.x;
    const int lane = tid & 31;
    const int wid  = tid >> 5;

    // strip partition per image: heights {176, 168, 168}, starts {0, 176, 344}
    const int sx     = blockIdx.x;
    const int r0     = (sx == 0) ? 0 : (176 + (sx - 1) * 168);
    const int rows   = (sx == 0) ? 176 : 168;
    const int chunks = rows / RC;

    const float* __restrict__ X = x   + (size_t)blockIdx.y * (HH * WW);
    float* __restrict__       O = out + (size_t)blockIdx.y * (HH * WW);

    // zero the "P[-1]" slots once (never touched by phases A/B)
    if (tid < 2 * RC) {
        float* p = (tid < RC) ? sS : sQ;
        p[(tid & (RC - 1)) * SPITCH + ZSLOT] = 0.f;
    }

    // ---- init vertical window: rows r0-16 .. r0+15 (lower reflect only) ----
    float vs = 0.f, vq = 0.f;
    #pragma unroll
    for (int d = -PD; d < PD; d++) {
        int rr = abs(r0 + d);                    // numpy 'reflect', lower edge
        float v = X[(rr << 9) + tid];
        vs += v; vq = fmaf(v, v, vq);
    }

    const int fcol = tid + (tid >> 4);           // phase-A store slot
    const float inv_n = 1.f / (float)(KS * KS);

    // ---- phase-C per-thread constants (oc == tid) ----
    const int oc  = tid;
    int hi = oc + 15; if (hi > 511) hi = 511;
    const int fhi = hi + (hi >> 4);
    const int lo  = oc - 17;
    const int flo = (lo >= 0) ? (lo + (lo >> 4)) : ZSLOT;     // P[-1] == 0
    const bool leftE  = (oc <= 15);              // window spills past column 0
    const bool rightE = (oc >= 497);             // window spills past column 511
    const int fle  = leftE  ? ((16 - oc) + ((16 - oc) >> 4)) : 0;
    const int fre2 = rightE ? ((1006 - oc) + ((1006 - oc) >> 4)) : 0;

    #pragma unroll 1
    for (int chunk = 0; chunk < chunks; chunk++) {
        const int ibase = r0 + chunk * RC;

        // ---- phase A: emit RC rows of vertical sums; slide the window ----
        #pragma unroll
        for (int rr = 0; rr < RC; rr++) {
            sS[rr * SPITCH + fcol] = vs;
            sQ[rr * SPITCH + fcol] = vq;
            int i  = ibase + rr;
            int ru = i + PD; ru = (ru < HH) ? ru : (2 * HH - 2 - ru);  // upper reflect only
            int rd = abs(i - PD);                                       // lower reflect only
            float va = X[(ru << 9) + tid];
            float vb = X[(rd << 9) + tid];
            vs += va - vb;
            vq = fmaf(va, va, fmaf(-vb, vb, vq));
        }
        __syncthreads();

        // ---- phase B: 16 warps, one (row,array) each; inclusive prefix over 512 ----
        {
            float* V = ((wid & 1) ? sQ : sS) + (wid >> 1) * SPITCH + lane * 17;
            float run = 0.f;
            #pragma unroll
            for (int k = 0; k < 16; k++) run += V[k];
            float tot = run;                     // warp-scan lane totals
            #pragma unroll
            for (int s = 1; s < 32; s <<= 1) {
                float u = __shfl_up_sync(0xffffffffu, tot, s);
                if (lane >= s) tot += u;
            }
            float acc = tot - run;               // exclusive offset
            #pragma unroll
            for (int k = 0; k < 16; k++) {
                acc += V[k];
                V[k] = acc;
            }
        }
        __syncthreads();

        // ---- phase C: box[oc] = P[hi]-P[lo] (+ reflected edge terms); finalize ----
        const float* Xc = X + (ibase << 9) + tid;
        float*       Oc = O + (ibase << 9) + tid;
        #pragma unroll
        for (int rr = 0; rr < RC; rr++) {
            const float* pS = sS + rr * SPITCH;
            const float* pQ = sQ + rr * SPITCH;
            float bS = pS[fhi] - pS[flo];
            float bQ = pQ[fhi] - pQ[flo];
            if (leftE)  { bS += pS[fle] - pS[0];    bQ += pQ[fle] - pQ[0]; }
            if (rightE) { bS += pS[541] - pS[fre2]; bQ += pQ[541] - pQ[fre2]; }
            float mean = bS * inv_n;
            float msq  = bQ * inv_n;
            float xc   = Xc[rr << 9];
            float var  = fabsf(fmaf(-mean, mean, msq));
            float r    = (xc - mean) * frsqrt(var + 1e-20f);
            r = fminf(fmaxf(r, -6.f), 6.f);
            Oc[rr << 9] = r;
        }
        __syncthreads();                          // protect sS/sQ for next phase A
    }
}

extern "C" void kernel_launch(void* const* d_in, const int* in_sizes, int n_in,
                              void* d_out, int out_size) {
    const float* x = (const float*)d_in[0];
    float* out = (float*)d_out;
    const int n_img = in_sizes[0] / (HH * WW);    // 96

    dim3 grid(3, n_img);                          // 3 x 96 = 288 blocks (~2/SM)
    localnorm_v8<<<grid, NT>>>(x, out);
}